// round 11
// baseline (speedup 1.0000x reference)
#include <cuda_runtime.h>
#include <cuda_bf16.h>
#include <math.h>

#define BB 4
#define TT 2048
#define DD 1024
#define HH 16
#define HD 64
#define MTOT (BB*TT)          // 8192

// GEMM tiling: CTA 256x128, warp tile 64x64, 8 warps (4m x 2n)  [R9 config]
#define GPITCH 36
#define GA_TILE (256*GPITCH)
#define GB_TILE (128*GPITCH)

// flash tiling (8 warps x 16 q-rows, ldmatrix fragments)
#define KPITCH 68
#define VPITCH 72
#define PPITCH 68
#define KS_BUF (64*KPITCH)
#define VS_BUF (64*VPITCH)

__device__ float g_q[MTOT * DD];
__device__ float g_k[MTOT * DD];
__device__ float g_v[MTOT * DD];
__device__ float g_attn[MTOT * DD];
__device__ float g_xr[MTOT * DD];     // tf32-rounded x
__device__ float g_wr[4 * DD * DD];   // tf32-rounded w_q,w_k,w_v,w_o

// ---------------------------------------------------------------------------
__device__ __forceinline__ unsigned smem_u32(const void* p) {
    unsigned r;
    asm("{ .reg .u64 t; cvta.to.shared.u64 t, %1; cvt.u32.u64 %0, t; }"
        : "=r"(r) : "l"(p));
    return r;
}
__device__ __forceinline__ void cp_async16(unsigned s, const void* g) {
    asm volatile("cp.async.cg.shared.global [%0], [%1], 16;" :: "r"(s), "l"(g));
}
__device__ __forceinline__ void cp_commit() { asm volatile("cp.async.commit_group;"); }
__device__ __forceinline__ void cp_wait0()  { asm volatile("cp.async.wait_group 0;"); }
__device__ __forceinline__ unsigned f2tf32(float f) {
    unsigned u;
    asm("cvt.rna.tf32.f32 %0, %1;" : "=r"(u) : "f"(f));
    return u;
}
__device__ __forceinline__ float roundtf(float f) { return __uint_as_float(f2tf32(f)); }
__device__ __forceinline__ void mma_tf32(float* c, const unsigned* a, const unsigned* b) {
    asm volatile(
        "mma.sync.aligned.m16n8k8.row.col.f32.tf32.tf32.f32 "
        "{%0,%1,%2,%3}, {%4,%5,%6,%7}, {%8,%9}, {%0,%1,%2,%3};"
        : "+f"(c[0]), "+f"(c[1]), "+f"(c[2]), "+f"(c[3])
        : "r"(a[0]), "r"(a[1]), "r"(a[2]), "r"(a[3]), "r"(b[0]), "r"(b[1]));
}
// one ldmatrix.x4 = four 8x4-b32 tiles; lane L gets element (L/4, L%4)
__device__ __forceinline__ void ldm_x4(unsigned* r, unsigned addr) {
    asm volatile("ldmatrix.sync.aligned.m8n8.x4.shared.b16 {%0,%1,%2,%3}, [%4];"
        : "=r"(r[0]), "=r"(r[1]), "=r"(r[2]), "=r"(r[3]) : "r"(addr) : "memory");
}

// ---------------------------------------------------------------------------
// prep: round arrays to tf32 grid
// ---------------------------------------------------------------------------
__global__ __launch_bounds__(256) void round_x_kernel(const float* __restrict__ in,
                                                      float* __restrict__ out)
{
    int i = blockIdx.x * blockDim.x + threadIdx.x;
    float4 v = ((const float4*)in)[i];
    v.x = roundtf(v.x); v.y = roundtf(v.y); v.z = roundtf(v.z); v.w = roundtf(v.w);
    ((float4*)out)[i] = v;
}
__global__ __launch_bounds__(256) void round_w_kernel(
    const float* __restrict__ w0, const float* __restrict__ w1,
    const float* __restrict__ w2, const float* __restrict__ w3,
    float* __restrict__ out)
{
    int i = blockIdx.x * blockDim.x + threadIdx.x;
    const int per = DD * DD / 4;
    int which = i / per;
    int off   = i - which * per;
    const float* src = (which == 0) ? w0 : (which == 1) ? w1 : (which == 2) ? w2 : w3;
    float4 v = ((const float4*)src)[off];
    v.x = roundtf(v.x); v.y = roundtf(v.y); v.z = roundtf(v.z); v.w = roundtf(v.w);
    ((float4*)out)[i] = v;
}

// ---------------------------------------------------------------------------
// TF32 GEMM body (R9 config): CTA 256x128, warp tile 64x64, scalar frags.
// Optional fused RoPE epilogue.
// ---------------------------------------------------------------------------
template<bool ROUND_OUT>
__device__ __forceinline__ void gemm_body(
    const float* __restrict__ A, const float* __restrict__ Bw,
    float* __restrict__ C, int M, int N, int K, float* sm,
    bool do_rope, const float* __restrict__ cosb, const float* __restrict__ sinb)
{
    float* sA = sm;                      // [2][256][GPITCH]
    float* sB = sm + 2 * GA_TILE;        // [2][128][GPITCH]

    const int tid  = threadIdx.x;
    const int lane = tid & 31;
    const int wid  = tid >> 5;
    const int wm   = wid & 3;
    const int wn   = wid >> 2;
    const int bm   = blockIdx.y * 256;
    const int bn   = blockIdx.x * 128;
    const int grp  = lane >> 2;
    const int tig  = lane & 3;

    const unsigned uA = smem_u32(sA);
    const unsigned uB = smem_u32(sB);

    float acc[4][8][4] = {};
    const int NK = K / 32;

    {
        #pragma unroll
        for (int i = 0; i < 8; i++) {
            int idx = tid + 256 * i;
            int row = idx >> 3;
            int c4  = idx & 7;
            cp_async16(uA + (row * GPITCH + c4 * 4) * 4,
                       A + (size_t)(bm + row) * K + c4 * 4);
        }
        #pragma unroll
        for (int i = 0; i < 4; i++) {
            int idx = tid + 256 * i;
            int row = idx >> 3;
            int c4  = idx & 7;
            cp_async16(uB + (row * GPITCH + c4 * 4) * 4,
                       Bw + (size_t)(bn + row) * K + c4 * 4);
        }
        cp_commit();
    }

    for (int kt = 0; kt < NK; kt++) {
        cp_wait0();
        __syncthreads();

        int nxt = kt + 1;
        if (nxt < NK) {
            int nb = nxt & 1;
            #pragma unroll
            for (int i = 0; i < 8; i++) {
                int idx = tid + 256 * i;
                int row = idx >> 3;
                int c4  = idx & 7;
                cp_async16(uA + (nb * GA_TILE + row * GPITCH + c4 * 4) * 4,
                           A + (size_t)(bm + row) * K + nxt * 32 + c4 * 4);
            }
            #pragma unroll
            for (int i = 0; i < 4; i++) {
                int idx = tid + 256 * i;
                int row = idx >> 3;
                int c4  = idx & 7;
                cp_async16(uB + (nb * GB_TILE + row * GPITCH + c4 * 4) * 4,
                           Bw + (size_t)(bn + row) * K + nxt * 32 + c4 * 4);
            }
            cp_commit();
        }

        const unsigned* As_ = (const unsigned*)(sA + (kt & 1) * GA_TILE);
        const unsigned* Bs_ = (const unsigned*)(sB + (kt & 1) * GB_TILE);

        #pragma unroll
        for (int ks = 0; ks < 4; ks++) {
            int kc = ks * 8 + tig;
            unsigned a[4][4], b[8][2];
            #pragma unroll
            for (int mi = 0; mi < 4; mi++) {
                const unsigned* p = As_ + (wm * 64 + mi * 16 + grp) * GPITCH + kc;
                a[mi][0] = p[0];
                a[mi][1] = p[8 * GPITCH];
                a[mi][2] = p[4];
                a[mi][3] = p[8 * GPITCH + 4];
            }
            #pragma unroll
            for (int ni = 0; ni < 8; ni++) {
                const unsigned* p = Bs_ + (wn * 64 + ni * 8 + grp) * GPITCH + kc;
                b[ni][0] = p[0];
                b[ni][1] = p[4];
            }
            #pragma unroll
            for (int mi = 0; mi < 4; mi++)
                #pragma unroll
                for (int ni = 0; ni < 8; ni++)
                    mma_tf32(acc[mi][ni], a[mi], b[ni]);
        }
    }

    if (do_rope) {
        #pragma unroll
        for (int mi = 0; mi < 4; mi++) {
            int r0 = bm + wm * 64 + mi * 16 + grp;
            int t0 = r0 & (TT - 1);
            int t1 = (r0 + 8) & (TT - 1);
            #pragma unroll
            for (int ni = 0; ni < 4; ni++) {
                int d   = ni * 8 + tig * 2;
                int col = bn + wn * 64 + d;
                float2 cl0 = *(const float2*)&cosb[t0 * HD + d];
                float2 ch0 = *(const float2*)&cosb[t0 * HD + d + 32];
                float2 sl0 = *(const float2*)&sinb[t0 * HD + d];
                float2 sh0 = *(const float2*)&sinb[t0 * HD + d + 32];
                float2 cl1 = *(const float2*)&cosb[t1 * HD + d];
                float2 ch1 = *(const float2*)&cosb[t1 * HD + d + 32];
                float2 sl1 = *(const float2*)&sinb[t1 * HD + d];
                float2 sh1 = *(const float2*)&sinb[t1 * HD + d + 32];

                float x1, x2;
                x1 = acc[mi][ni][0];   x2 = acc[mi][ni + 4][0];
                float o00 = x1 * cl0.x - x2 * sl0.x;
                float o04 = x2 * ch0.x + x1 * sh0.x;
                x1 = acc[mi][ni][1];   x2 = acc[mi][ni + 4][1];
                float o01 = x1 * cl0.y - x2 * sl0.y;
                float o05 = x2 * ch0.y + x1 * sh0.y;
                x1 = acc[mi][ni][2];   x2 = acc[mi][ni + 4][2];
                float o02 = x1 * cl1.x - x2 * sl1.x;
                float o06 = x2 * ch1.x + x1 * sh1.x;
                x1 = acc[mi][ni][3];   x2 = acc[mi][ni + 4][3];
                float o03 = x1 * cl1.y - x2 * sl1.y;
                float o07 = x2 * ch1.y + x1 * sh1.y;

                *(float2*)&C[(size_t)r0 * N + col] =
                    make_float2(roundtf(o00), roundtf(o01));
                *(float2*)&C[(size_t)(r0 + 8) * N + col] =
                    make_float2(roundtf(o02), roundtf(o03));
                *(float2*)&C[(size_t)r0 * N + col + 32] =
                    make_float2(roundtf(o04), roundtf(o05));
                *(float2*)&C[(size_t)(r0 + 8) * N + col + 32] =
                    make_float2(roundtf(o06), roundtf(o07));
            }
        }
    } else {
        #pragma unroll
        for (int mi = 0; mi < 4; mi++) {
            int r0 = bm + wm * 64 + mi * 16 + grp;
            #pragma unroll
            for (int ni = 0; ni < 8; ni++) {
                int col = bn + wn * 64 + ni * 8 + tig * 2;
                float2 lo, hi;
                if (ROUND_OUT) {
                    lo = make_float2(roundtf(acc[mi][ni][0]), roundtf(acc[mi][ni][1]));
                    hi = make_float2(roundtf(acc[mi][ni][2]), roundtf(acc[mi][ni][3]));
                } else {
                    lo = make_float2(acc[mi][ni][0], acc[mi][ni][1]);
                    hi = make_float2(acc[mi][ni][2], acc[mi][ni][3]);
                }
                *(float2*)&C[(size_t)r0 * N + col]       = lo;
                *(float2*)&C[(size_t)(r0 + 8) * N + col] = hi;
            }
        }
    }
}

__global__ __launch_bounds__(256) void gemm_qkv_kernel(
    const float* __restrict__ A, const float* __restrict__ W,
    float* __restrict__ Cq, float* __restrict__ Ck, float* __restrict__ Cv,
    const float* __restrict__ cosb, const float* __restrict__ sinb)
{
    extern __shared__ float sm[];
    int z = blockIdx.z;
    float* C = (z == 0) ? Cq : (z == 1) ? Ck : Cv;
    gemm_body<true>(A, W + (size_t)z * DD * DD, C, MTOT, DD, DD, sm,
                    /*do_rope=*/(z != 2), cosb, sinb);
}
__global__ __launch_bounds__(256) void gemm_out_kernel(
    const float* __restrict__ A, const float* __restrict__ W, float* __restrict__ C)
{
    extern __shared__ float sm[];
    gemm_body<false>(A, W, C, MTOT, DD, DD, sm, false, nullptr, nullptr);
}

// ---------------------------------------------------------------------------
// Tensor-core causal flash attention. BQ=128, 8 warps x 16 q-rows,
// ldmatrix fragments (Q/K/P), V scalar. 2 CTAs/SM (regs pinned <=128).
// Longest CTAs (high qb) launch first.
// ---------------------------------------------------------------------------
__global__ __launch_bounds__(256, 2) void flash_attn_tc_kernel(
    const float* __restrict__ Qg, const float* __restrict__ Kg,
    const float* __restrict__ Vg, float* __restrict__ Og)
{
    extern __shared__ float sm[];
    float* Ks = sm;
    float* Vs = Ks + 2 * KS_BUF;
    float* Ps = Vs + 2 * VS_BUF;          // [128][PPITCH]

    const int tid  = threadIdx.x;
    const int lane = tid & 31;
    const int w    = tid >> 5;            // warp 0..7
    const int grp  = lane >> 2;
    const int tig  = lane & 3;
    const int qb   = (TT/128 - 1) - blockIdx.x;   // descending work order
    const int bh   = blockIdx.y;
    const int b    = bh >> 4;
    const int h    = bh & 15;

    const size_t headoff = (size_t)(b * TT) * DD + (size_t)h * HD;
    const float scale = 0.125f;
    const unsigned uK = smem_u32(Ks);
    const unsigned uV = smem_u32(Vs);
    const unsigned uP = smem_u32(Ps);

    // ldmatrix lane addressing
    const int l15  = lane & 15;
    const int lhi  = (lane >> 4) & 1;
    const int brow = (lane & 7) + ((lane & 16) ? 8 : 0);
    const int bsel = (lane & 8) ? 4 : 0;
    const unsigned kAddr = uK + ((brow * KPITCH) + bsel) * 4;
    const unsigned pAddr = uP + (((w * 16 + l15) * PPITCH) + lhi * 4) * 4;

    // stage Q tile [128 x 64] into Ps
    #pragma unroll
    for (int i = 0; i < 8; i++) {
        int idx = i * 256 + tid;          // 0..2047
        int row = idx >> 4;
        int c4  = idx & 15;
        float4 v4 = *(const float4*)&Qg[headoff + (size_t)(qb*128 + row) * DD + c4*4];
        *(float4*)&Ps[row * PPITCH + c4*4] = v4;
    }
    __syncthreads();

    unsigned qa[8][4];                    // Q frags via ldmatrix
    #pragma unroll
    for (int ks = 0; ks < 8; ks++)
        ldm_x4(qa[ks], pAddr + (ks * 8) * 4);
    __syncwarp();

    float acc_o[8][4] = {};
    float m_lo = -1e30f, m_hi = -1e30f;
    float l_lo = 0.0f,   l_hi = 0.0f;

    const int kb_max = 2 * qb + 1;
    const int q_lo = qb * 128 + w * 16 + grp;
    const int q_hi = q_lo + 8;

    {
        #pragma unroll
        for (int i = 0; i < 8; i++) {
            int idx = i * 256 + tid;
            int row = (idx >> 4) & 63;
            int c4  = idx & 15;
            size_t goff = headoff + (size_t)row * DD + c4 * 4;
            if (idx < 1024)
                cp_async16(uK + (row * KPITCH + c4 * 4) * 4, Kg + goff);
            else
                cp_async16(uV + (row * VPITCH + c4 * 4) * 4, Vg + goff);
        }
        cp_commit();
    }

    for (int kb = 0; kb <= kb_max; kb++) {
        cp_wait0();
        __syncthreads();

        if (kb < kb_max) {
            int nb = (kb + 1) & 1;
            #pragma unroll
            for (int i = 0; i < 8; i++) {
                int idx = i * 256 + tid;
                int row = (idx >> 4) & 63;
                int c4  = idx & 15;
                size_t goff = headoff + (size_t)((kb+1)*64 + row) * DD + c4 * 4;
                if (idx < 1024)
                    cp_async16(uK + (nb * KS_BUF + row * KPITCH + c4 * 4) * 4, Kg + goff);
                else
                    cp_async16(uV + (nb * VS_BUF + row * VPITCH + c4 * 4) * 4, Vg + goff);
            }
            cp_commit();
        }

        const unsigned kBuf = kAddr + (kb & 1) * KS_BUF * 4;
        const unsigned* Vs_ = (const unsigned*)(Vs + (kb & 1) * VS_BUF);

        // ---- S = Q @ K^T (K frags via ldmatrix) ----
        float acc_s[8][4] = {};
        #pragma unroll
        for (int ks = 0; ks < 8; ks++) {
            unsigned bfr[8][2];
            #pragma unroll
            for (int pr = 0; pr < 4; pr++) {
                unsigned t[4];
                ldm_x4(t, kBuf + (pr * 16 * KPITCH + ks * 8) * 4);
                bfr[2*pr][0] = t[0]; bfr[2*pr][1] = t[1];
                bfr[2*pr+1][0] = t[2]; bfr[2*pr+1][1] = t[3];
            }
            #pragma unroll
            for (int ni = 0; ni < 8; ni++)
                mma_tf32(acc_s[ni], qa[ks], bfr[ni]);
        }

        // ---- scale + causal mask ----
        const bool diag = (kb >= 2 * qb);
        #pragma unroll
        for (int ni = 0; ni < 8; ni++) {
            int k0 = kb * 64 + ni * 8 + 2 * tig;
            if (diag) {
                acc_s[ni][0] = (k0     <= q_lo) ? acc_s[ni][0] * scale : -1e30f;
                acc_s[ni][1] = (k0 + 1 <= q_lo) ? acc_s[ni][1] * scale : -1e30f;
                acc_s[ni][2] = (k0     <= q_hi) ? acc_s[ni][2] * scale : -1e30f;
                acc_s[ni][3] = (k0 + 1 <= q_hi) ? acc_s[ni][3] * scale : -1e30f;
            } else {
                acc_s[ni][0] *= scale; acc_s[ni][1] *= scale;
                acc_s[ni][2] *= scale; acc_s[ni][3] *= scale;
            }
        }

        // ---- online softmax ----
        float tm_lo = -1e30f, tm_hi = -1e30f;
        #pragma unroll
        for (int ni = 0; ni < 8; ni++) {
            tm_lo = fmaxf(tm_lo, fmaxf(acc_s[ni][0], acc_s[ni][1]));
            tm_hi = fmaxf(tm_hi, fmaxf(acc_s[ni][2], acc_s[ni][3]));
        }
        tm_lo = fmaxf(tm_lo, __shfl_xor_sync(0xffffffffu, tm_lo, 1));
        tm_lo = fmaxf(tm_lo, __shfl_xor_sync(0xffffffffu, tm_lo, 2));
        tm_hi = fmaxf(tm_hi, __shfl_xor_sync(0xffffffffu, tm_hi, 1));
        tm_hi = fmaxf(tm_hi, __shfl_xor_sync(0xffffffffu, tm_hi, 2));

        float mn_lo = fmaxf(m_lo, tm_lo);
        float mn_hi = fmaxf(m_hi, tm_hi);
        float f_lo = __expf(m_lo - mn_lo);
        float f_hi = __expf(m_hi - mn_hi);
        m_lo = mn_lo; m_hi = mn_hi;

        // P = exp(S - m); stored tf32-rounded (ldmatrix-compatible; sums
        // use unrounded values, identical numerics to cvt-at-load)
        float rs_lo = 0.0f, rs_hi = 0.0f;
        float* Pw = Ps + (w * 16 + grp) * PPITCH;
        #pragma unroll
        for (int ni = 0; ni < 8; ni++) {
            float p0 = __expf(acc_s[ni][0] - mn_lo);
            float p1 = __expf(acc_s[ni][1] - mn_lo);
            float p2 = __expf(acc_s[ni][2] - mn_hi);
            float p3 = __expf(acc_s[ni][3] - mn_hi);
            rs_lo += p0 + p1;
            rs_hi += p2 + p3;
            *(float2*)&Pw[ni * 8 + 2 * tig] =
                make_float2(roundtf(p0), roundtf(p1));
            *(float2*)&Pw[8 * PPITCH + ni * 8 + 2 * tig] =
                make_float2(roundtf(p2), roundtf(p3));
        }
        rs_lo += __shfl_xor_sync(0xffffffffu, rs_lo, 1);
        rs_lo += __shfl_xor_sync(0xffffffffu, rs_lo, 2);
        rs_hi += __shfl_xor_sync(0xffffffffu, rs_hi, 1);
        rs_hi += __shfl_xor_sync(0xffffffffu, rs_hi, 2);
        l_lo = l_lo * f_lo + rs_lo;
        l_hi = l_hi * f_hi + rs_hi;

        #pragma unroll
        for (int ni = 0; ni < 8; ni++) {
            acc_o[ni][0] *= f_lo; acc_o[ni][1] *= f_lo;
            acc_o[ni][2] *= f_hi; acc_o[ni][3] *= f_hi;
        }

        __syncwarp();

        // ---- O += P @ V (P via ldmatrix; V scalar) ----
        #pragma unroll
        for (int kc = 0; kc < 8; kc++) {
            unsigned pa[4];
            ldm_x4(pa, pAddr + (kc * 8) * 4);
            unsigned bv[8][2];
            #pragma unroll
            for (int ni = 0; ni < 8; ni++) {
                const unsigned* p = Vs_ + (kc * 8 + tig) * VPITCH + ni * 8 + grp;
                bv[ni][0] = p[0];
                bv[ni][1] = p[4 * VPITCH];
            }
            #pragma unroll
            for (int ni = 0; ni < 8; ni++)
                mma_tf32(acc_o[ni], pa, bv[ni]);
        }
        __syncwarp();
    }

    // ---- epilogue ----
    float il_lo = 1.0f / l_lo;
    float il_hi = 1.0f / l_hi;
    #pragma unroll
    for (int ni = 0; ni < 8; ni++) {
        int col = ni * 8 + 2 * tig;
        *(float2*)&Og[headoff + (size_t)q_lo * DD + col] =
            make_float2(roundtf(acc_o[ni][0] * il_lo), roundtf(acc_o[ni][1] * il_lo));
        *(float2*)&Og[headoff + (size_t)q_hi * DD + col] =
            make_float2(roundtf(acc_o[ni][2] * il_hi), roundtf(acc_o[ni][3] * il_hi));
    }
}

// ---------------------------------------------------------------------------
extern "C" void kernel_launch(void* const* d_in, const int* in_sizes, int n_in,
                              void* d_out, int out_size)
{
    const float* x    = (const float*)d_in[0];
    const float* cosb = (const float*)d_in[1];
    const float* sinb = (const float*)d_in[2];
    const float* w_q  = (const float*)d_in[3];
    const float* w_k  = (const float*)d_in[4];
    const float* w_v  = (const float*)d_in[5];
    const float* w_o  = (const float*)d_in[6];
    float* out = (float*)d_out;

    float *q, *k, *v, *attn, *xr, *wr;
    cudaGetSymbolAddress((void**)&q,    g_q);
    cudaGetSymbolAddress((void**)&k,    g_k);
    cudaGetSymbolAddress((void**)&v,    g_v);
    cudaGetSymbolAddress((void**)&attn, g_attn);
    cudaGetSymbolAddress((void**)&xr,   g_xr);
    cudaGetSymbolAddress((void**)&wr,   g_wr);

    const int gm_smem = (2 * GA_TILE + 2 * GB_TILE) * sizeof(float);   // 110592
    cudaFuncSetAttribute(gemm_qkv_kernel,
                         cudaFuncAttributeMaxDynamicSharedMemorySize, gm_smem);
    cudaFuncSetAttribute(gemm_out_kernel,
                         cudaFuncAttributeMaxDynamicSharedMemorySize, gm_smem);

    const int fa_smem = (2 * KS_BUF + 2 * VS_BUF + 128 * PPITCH) * sizeof(float);
    cudaFuncSetAttribute(flash_attn_tc_kernel,
                         cudaFuncAttributeMaxDynamicSharedMemorySize, fa_smem);

    round_x_kernel<<<(MTOT * DD / 4) / 256, 256>>>(x, xr);
    round_w_kernel<<<(4 * DD * DD / 4) / 256, 256>>>(w_q, w_k, w_v, w_o, wr);

    // fused QKV projection + RoPE
    dim3 qkvgrid(DD / 128, MTOT / 256, 3);   // (8, 32, 3)
    gemm_qkv_kernel<<<qkvgrid, 256, gm_smem>>>(xr, wr, q, k, v, cosb, sinb);

    flash_attn_tc_kernel<<<dim3(TT / 128, BB * HH), 256, fa_smem>>>(q, k, v, attn);

    dim3 ogrid(DD / 128, MTOT / 256);        // (8, 32)
    gemm_out_kernel<<<ogrid, 256, gm_smem>>>(attn, wr + (size_t)3 * DD * DD, out);
}

// round 13
// speedup vs baseline: 1.0402x; 1.0402x over previous
#include <cuda_runtime.h>
#include <cuda_bf16.h>
#include <math.h>

#define BB 4
#define TT 2048
#define DD 1024
#define HH 16
#define HD 64
#define MTOT (BB*TT)          // 8192

// GEMM tiling: CTA 256x128, warp tile 64x64, 8 warps (4m x 2n)  [R9 measured-best]
#define GPITCH 36
#define GA_TILE (256*GPITCH)
#define GB_TILE (128*GPITCH)

// flash tiling (4 warps x 32 q-rows, ldmatrix frags)  [R10 measured-best]
#define KPITCH 68
#define VPITCH 72
#define PPITCH 68
#define KS_BUF (64*KPITCH)
#define VS_BUF (64*VPITCH)

__device__ float g_q[MTOT * DD];
__device__ float g_k[MTOT * DD];
__device__ float g_v[MTOT * DD];
__device__ float g_attn[MTOT * DD];
__device__ float g_xr[MTOT * DD];     // tf32-rounded x
__device__ float g_wr[4 * DD * DD];   // tf32-rounded w_q,w_k,w_v,w_o

// ---------------------------------------------------------------------------
__device__ __forceinline__ unsigned smem_u32(const void* p) {
    unsigned r;
    asm("{ .reg .u64 t; cvta.to.shared.u64 t, %1; cvt.u32.u64 %0, t; }"
        : "=r"(r) : "l"(p));
    return r;
}
__device__ __forceinline__ void cp_async16(unsigned s, const void* g) {
    asm volatile("cp.async.cg.shared.global [%0], [%1], 16;" :: "r"(s), "l"(g));
}
__device__ __forceinline__ void cp_commit() { asm volatile("cp.async.commit_group;"); }
__device__ __forceinline__ void cp_wait0()  { asm volatile("cp.async.wait_group 0;"); }
__device__ __forceinline__ unsigned f2tf32(float f) {
    unsigned u;
    asm("cvt.rna.tf32.f32 %0, %1;" : "=r"(u) : "f"(f));
    return u;
}
__device__ __forceinline__ float roundtf(float f) { return __uint_as_float(f2tf32(f)); }
__device__ __forceinline__ void mma_tf32(float* c, const unsigned* a, const unsigned* b) {
    asm volatile(
        "mma.sync.aligned.m16n8k8.row.col.f32.tf32.tf32.f32 "
        "{%0,%1,%2,%3}, {%4,%5,%6,%7}, {%8,%9}, {%0,%1,%2,%3};"
        : "+f"(c[0]), "+f"(c[1]), "+f"(c[2]), "+f"(c[3])
        : "r"(a[0]), "r"(a[1]), "r"(a[2]), "r"(a[3]), "r"(b[0]), "r"(b[1]));
}
// one ldmatrix.x4 = four 8x4-b32 tiles; lane L gets element (L/4, L%4)
__device__ __forceinline__ void ldm_x4(unsigned* r, unsigned addr) {
    asm volatile("ldmatrix.sync.aligned.m8n8.x4.shared.b16 {%0,%1,%2,%3}, [%4];"
        : "=r"(r[0]), "=r"(r[1]), "=r"(r[2]), "=r"(r[3]) : "r"(addr) : "memory");
}

// ---------------------------------------------------------------------------
// prep: round arrays to tf32 grid
// ---------------------------------------------------------------------------
__global__ __launch_bounds__(256) void round_x_kernel(const float* __restrict__ in,
                                                      float* __restrict__ out)
{
    int i = blockIdx.x * blockDim.x + threadIdx.x;
    float4 v = ((const float4*)in)[i];
    v.x = roundtf(v.x); v.y = roundtf(v.y); v.z = roundtf(v.z); v.w = roundtf(v.w);
    ((float4*)out)[i] = v;
}
__global__ __launch_bounds__(256) void round_w_kernel(
    const float* __restrict__ w0, const float* __restrict__ w1,
    const float* __restrict__ w2, const float* __restrict__ w3,
    float* __restrict__ out)
{
    int i = blockIdx.x * blockDim.x + threadIdx.x;
    const int per = DD * DD / 4;
    int which = i / per;
    int off   = i - which * per;
    const float* src = (which == 0) ? w0 : (which == 1) ? w1 : (which == 2) ? w2 : w3;
    float4 v = ((const float4*)src)[off];
    v.x = roundtf(v.x); v.y = roundtf(v.y); v.z = roundtf(v.z); v.w = roundtf(v.w);
    ((float4*)out)[i] = v;
}

// ---------------------------------------------------------------------------
// TF32 GEMM body (R9 config): CTA 256x128, warp tile 64x64, scalar frags.
// Optional fused RoPE epilogue.
// ---------------------------------------------------------------------------
template<bool ROUND_OUT>
__device__ __forceinline__ void gemm_body(
    const float* __restrict__ A, const float* __restrict__ Bw,
    float* __restrict__ C, int M, int N, int K, float* sm,
    bool do_rope, const float* __restrict__ cosb, const float* __restrict__ sinb)
{
    float* sA = sm;                      // [2][256][GPITCH]
    float* sB = sm + 2 * GA_TILE;        // [2][128][GPITCH]

    const int tid  = threadIdx.x;
    const int lane = tid & 31;
    const int wid  = tid >> 5;
    const int wm   = wid & 3;
    const int wn   = wid >> 2;
    const int bm   = blockIdx.y * 256;
    const int bn   = blockIdx.x * 128;
    const int grp  = lane >> 2;
    const int tig  = lane & 3;

    const unsigned uA = smem_u32(sA);
    const unsigned uB = smem_u32(sB);

    float acc[4][8][4] = {};
    const int NK = K / 32;

    {
        #pragma unroll
        for (int i = 0; i < 8; i++) {
            int idx = tid + 256 * i;
            int row = idx >> 3;
            int c4  = idx & 7;
            cp_async16(uA + (row * GPITCH + c4 * 4) * 4,
                       A + (size_t)(bm + row) * K + c4 * 4);
        }
        #pragma unroll
        for (int i = 0; i < 4; i++) {
            int idx = tid + 256 * i;
            int row = idx >> 3;
            int c4  = idx & 7;
            cp_async16(uB + (row * GPITCH + c4 * 4) * 4,
                       Bw + (size_t)(bn + row) * K + c4 * 4);
        }
        cp_commit();
    }

    for (int kt = 0; kt < NK; kt++) {
        cp_wait0();
        __syncthreads();

        int nxt = kt + 1;
        if (nxt < NK) {
            int nb = nxt & 1;
            #pragma unroll
            for (int i = 0; i < 8; i++) {
                int idx = tid + 256 * i;
                int row = idx >> 3;
                int c4  = idx & 7;
                cp_async16(uA + (nb * GA_TILE + row * GPITCH + c4 * 4) * 4,
                           A + (size_t)(bm + row) * K + nxt * 32 + c4 * 4);
            }
            #pragma unroll
            for (int i = 0; i < 4; i++) {
                int idx = tid + 256 * i;
                int row = idx >> 3;
                int c4  = idx & 7;
                cp_async16(uB + (nb * GB_TILE + row * GPITCH + c4 * 4) * 4,
                           Bw + (size_t)(bn + row) * K + nxt * 32 + c4 * 4);
            }
            cp_commit();
        }

        const unsigned* As_ = (const unsigned*)(sA + (kt & 1) * GA_TILE);
        const unsigned* Bs_ = (const unsigned*)(sB + (kt & 1) * GB_TILE);

        #pragma unroll
        for (int ks = 0; ks < 4; ks++) {
            int kc = ks * 8 + tig;
            unsigned a[4][4], b[8][2];
            #pragma unroll
            for (int mi = 0; mi < 4; mi++) {
                const unsigned* p = As_ + (wm * 64 + mi * 16 + grp) * GPITCH + kc;
                a[mi][0] = p[0];
                a[mi][1] = p[8 * GPITCH];
                a[mi][2] = p[4];
                a[mi][3] = p[8 * GPITCH + 4];
            }
            #pragma unroll
            for (int ni = 0; ni < 8; ni++) {
                const unsigned* p = Bs_ + (wn * 64 + ni * 8 + grp) * GPITCH + kc;
                b[ni][0] = p[0];
                b[ni][1] = p[4];
            }
            #pragma unroll
            for (int mi = 0; mi < 4; mi++)
                #pragma unroll
                for (int ni = 0; ni < 8; ni++)
                    mma_tf32(acc[mi][ni], a[mi], b[ni]);
        }
    }

    if (do_rope) {
        #pragma unroll
        for (int mi = 0; mi < 4; mi++) {
            int r0 = bm + wm * 64 + mi * 16 + grp;
            int t0 = r0 & (TT - 1);
            int t1 = (r0 + 8) & (TT - 1);
            #pragma unroll
            for (int ni = 0; ni < 4; ni++) {
                int d   = ni * 8 + tig * 2;
                int col = bn + wn * 64 + d;
                float2 cl0 = *(const float2*)&cosb[t0 * HD + d];
                float2 ch0 = *(const float2*)&cosb[t0 * HD + d + 32];
                float2 sl0 = *(const float2*)&sinb[t0 * HD + d];
                float2 sh0 = *(const float2*)&sinb[t0 * HD + d + 32];
                float2 cl1 = *(const float2*)&cosb[t1 * HD + d];
                float2 ch1 = *(const float2*)&cosb[t1 * HD + d + 32];
                float2 sl1 = *(const float2*)&sinb[t1 * HD + d];
                float2 sh1 = *(const float2*)&sinb[t1 * HD + d + 32];

                float x1, x2;
                x1 = acc[mi][ni][0];   x2 = acc[mi][ni + 4][0];
                float o00 = x1 * cl0.x - x2 * sl0.x;
                float o04 = x2 * ch0.x + x1 * sh0.x;
                x1 = acc[mi][ni][1];   x2 = acc[mi][ni + 4][1];
                float o01 = x1 * cl0.y - x2 * sl0.y;
                float o05 = x2 * ch0.y + x1 * sh0.y;
                x1 = acc[mi][ni][2];   x2 = acc[mi][ni + 4][2];
                float o02 = x1 * cl1.x - x2 * sl1.x;
                float o06 = x2 * ch1.x + x1 * sh1.x;
                x1 = acc[mi][ni][3];   x2 = acc[mi][ni + 4][3];
                float o03 = x1 * cl1.y - x2 * sl1.y;
                float o07 = x2 * ch1.y + x1 * sh1.y;

                *(float2*)&C[(size_t)r0 * N + col] =
                    make_float2(roundtf(o00), roundtf(o01));
                *(float2*)&C[(size_t)(r0 + 8) * N + col] =
                    make_float2(roundtf(o02), roundtf(o03));
                *(float2*)&C[(size_t)r0 * N + col + 32] =
                    make_float2(roundtf(o04), roundtf(o05));
                *(float2*)&C[(size_t)(r0 + 8) * N + col + 32] =
                    make_float2(roundtf(o06), roundtf(o07));
            }
        }
    } else {
        #pragma unroll
        for (int mi = 0; mi < 4; mi++) {
            int r0 = bm + wm * 64 + mi * 16 + grp;
            #pragma unroll
            for (int ni = 0; ni < 8; ni++) {
                int col = bn + wn * 64 + ni * 8 + tig * 2;
                float2 lo, hi;
                if (ROUND_OUT) {
                    lo = make_float2(roundtf(acc[mi][ni][0]), roundtf(acc[mi][ni][1]));
                    hi = make_float2(roundtf(acc[mi][ni][2]), roundtf(acc[mi][ni][3]));
                } else {
                    lo = make_float2(acc[mi][ni][0], acc[mi][ni][1]);
                    hi = make_float2(acc[mi][ni][2], acc[mi][ni][3]);
                }
                *(float2*)&C[(size_t)r0 * N + col]       = lo;
                *(float2*)&C[(size_t)(r0 + 8) * N + col] = hi;
            }
        }
    }
}

__global__ __launch_bounds__(256) void gemm_qkv_kernel(
    const float* __restrict__ A, const float* __restrict__ W,
    float* __restrict__ Cq, float* __restrict__ Ck, float* __restrict__ Cv,
    const float* __restrict__ cosb, const float* __restrict__ sinb)
{
    extern __shared__ float sm[];
    int z = blockIdx.z;
    float* C = (z == 0) ? Cq : (z == 1) ? Ck : Cv;
    gemm_body<true>(A, W + (size_t)z * DD * DD, C, MTOT, DD, DD, sm,
                    /*do_rope=*/(z != 2), cosb, sinb);
}
__global__ __launch_bounds__(256) void gemm_out_kernel(
    const float* __restrict__ A, const float* __restrict__ W, float* __restrict__ C)
{
    extern __shared__ float sm[];
    gemm_body<false>(A, W, C, MTOT, DD, DD, sm, false, nullptr, nullptr);
}

// ---------------------------------------------------------------------------
// Tensor-core causal flash attention (R10 measured-best config).
// BQ=128, 4 warps x 32 q-rows. Q/K/P fragments via ldmatrix; V scalar.
// Longest CTAs (high qb) launch first.
// ---------------------------------------------------------------------------
__global__ __launch_bounds__(128) void flash_attn_tc_kernel(
    const float* __restrict__ Qg, const float* __restrict__ Kg,
    const float* __restrict__ Vg, float* __restrict__ Og)
{
    extern __shared__ float sm[];
    float* Ks = sm;
    float* Vs = Ks + 2 * KS_BUF;
    float* Ps = Vs + 2 * VS_BUF;          // [128][PPITCH]

    const int tid  = threadIdx.x;
    const int lane = tid & 31;
    const int w    = tid >> 5;            // warp 0..3
    const int grp  = lane >> 2;
    const int tig  = lane & 3;
    const int qb   = (TT/128 - 1) - blockIdx.x;   // descending work order
    const int bh   = blockIdx.y;
    const int b    = bh >> 4;
    const int h    = bh & 15;

    const size_t headoff = (size_t)(b * TT) * DD + (size_t)h * HD;
    const float scale = 0.125f;
    const unsigned uK = smem_u32(Ks);
    const unsigned uV = smem_u32(Vs);
    const unsigned uP = smem_u32(Ps);

    // ldmatrix lane addressing
    const int l15  = lane & 15;
    const int lhi  = (lane >> 4) & 1;
    const int brow = (lane & 7) + ((lane & 16) ? 8 : 0);
    const int bsel = (lane & 8) ? 4 : 0;
    const unsigned kAddr = uK + ((brow * KPITCH) + bsel) * 4;
    const unsigned pAddr = uP + (((w * 32 + l15) * PPITCH) + lhi * 4) * 4;

    // stage Q tile [128 x 64] into Ps
    #pragma unroll
    for (int i = 0; i < 16; i++) {
        int idx = i * 128 + tid;          // 0..2047
        int row = idx >> 4;
        int c4  = idx & 15;
        float4 v4 = *(const float4*)&Qg[headoff + (size_t)(qb*128 + row) * DD + c4*4];
        *(float4*)&Ps[row * PPITCH + c4*4] = v4;
    }
    __syncthreads();

    unsigned qa[2][8][4];                 // two 16-row sets (Q frags, ldmatrix)
    #pragma unroll
    for (int st = 0; st < 2; st++)
        #pragma unroll
        for (int ks = 0; ks < 8; ks++)
            ldm_x4(qa[st][ks], pAddr + (st * 16 * PPITCH + ks * 8) * 4);
    __syncwarp();

    float acc_o[2][8][4] = {};
    float mrow[4] = {-1e30f, -1e30f, -1e30f, -1e30f};
    float lrow[4] = {};

    const int kb_max = 2 * qb + 1;
    const int qrow0 = qb * 128 + w * 32 + grp;

    {
        #pragma unroll
        for (int i = 0; i < 16; i++) {
            int idx = i * 128 + tid;
            int row = (idx >> 4) & 63;
            int c4  = idx & 15;
            size_t goff = headoff + (size_t)row * DD + c4 * 4;
            if (idx < 1024)
                cp_async16(uK + (row * KPITCH + c4 * 4) * 4, Kg + goff);
            else
                cp_async16(uV + (row * VPITCH + c4 * 4) * 4, Vg + goff);
        }
        cp_commit();
    }

    for (int kb = 0; kb <= kb_max; kb++) {
        cp_wait0();
        __syncthreads();

        if (kb < kb_max) {
            int nb = (kb + 1) & 1;
            #pragma unroll
            for (int i = 0; i < 16; i++) {
                int idx = i * 128 + tid;
                int row = (idx >> 4) & 63;
                int c4  = idx & 15;
                size_t goff = headoff + (size_t)((kb+1)*64 + row) * DD + c4 * 4;
                if (idx < 1024)
                    cp_async16(uK + (nb * KS_BUF + row * KPITCH + c4 * 4) * 4, Kg + goff);
                else
                    cp_async16(uV + (nb * VS_BUF + row * VPITCH + c4 * 4) * 4, Vg + goff);
            }
            cp_commit();
        }

        const unsigned kBuf = kAddr + (kb & 1) * KS_BUF * 4;
        const unsigned* Vs_ = (const unsigned*)(Vs + (kb & 1) * VS_BUF);

        // ---- S = Q @ K^T for both row sets (K frags via ldmatrix) ----
        float acc_s[2][8][4] = {};
        #pragma unroll
        for (int ks = 0; ks < 8; ks++) {
            unsigned bfr[8][2];
            #pragma unroll
            for (int pr = 0; pr < 4; pr++) {
                unsigned t[4];
                ldm_x4(t, kBuf + (pr * 16 * KPITCH + ks * 8) * 4);
                bfr[2*pr][0] = t[0]; bfr[2*pr][1] = t[1];
                bfr[2*pr+1][0] = t[2]; bfr[2*pr+1][1] = t[3];
            }
            #pragma unroll
            for (int ni = 0; ni < 8; ni++) {
                mma_tf32(acc_s[0][ni], qa[0][ks], bfr[ni]);
                mma_tf32(acc_s[1][ni], qa[1][ks], bfr[ni]);
            }
        }

        // ---- scale + causal mask ----
        const bool diag = (kb >= 2 * qb);
        #pragma unroll
        for (int st = 0; st < 2; st++) {
            int qlo = qrow0 + st * 16;
            int qhi = qlo + 8;
            #pragma unroll
            for (int ni = 0; ni < 8; ni++) {
                int k0 = kb * 64 + ni * 8 + 2 * tig;
                if (diag) {
                    acc_s[st][ni][0] = (k0     <= qlo) ? acc_s[st][ni][0] * scale : -1e30f;
                    acc_s[st][ni][1] = (k0 + 1 <= qlo) ? acc_s[st][ni][1] * scale : -1e30f;
                    acc_s[st][ni][2] = (k0     <= qhi) ? acc_s[st][ni][2] * scale : -1e30f;
                    acc_s[st][ni][3] = (k0 + 1 <= qhi) ? acc_s[st][ni][3] * scale : -1e30f;
                } else {
                    acc_s[st][ni][0] *= scale; acc_s[st][ni][1] *= scale;
                    acc_s[st][ni][2] *= scale; acc_s[st][ni][3] *= scale;
                }
            }
        }

        // ---- online softmax; P written tf32-rounded ----
        #pragma unroll
        for (int st = 0; st < 2; st++) {
            float tm_lo = -1e30f, tm_hi = -1e30f;
            #pragma unroll
            for (int ni = 0; ni < 8; ni++) {
                tm_lo = fmaxf(tm_lo, fmaxf(acc_s[st][ni][0], acc_s[st][ni][1]));
                tm_hi = fmaxf(tm_hi, fmaxf(acc_s[st][ni][2], acc_s[st][ni][3]));
            }
            tm_lo = fmaxf(tm_lo, __shfl_xor_sync(0xffffffffu, tm_lo, 1));
            tm_lo = fmaxf(tm_lo, __shfl_xor_sync(0xffffffffu, tm_lo, 2));
            tm_hi = fmaxf(tm_hi, __shfl_xor_sync(0xffffffffu, tm_hi, 1));
            tm_hi = fmaxf(tm_hi, __shfl_xor_sync(0xffffffffu, tm_hi, 2));

            float mn_lo = fmaxf(mrow[st*2+0], tm_lo);
            float mn_hi = fmaxf(mrow[st*2+1], tm_hi);
            float f_lo = __expf(mrow[st*2+0] - mn_lo);
            float f_hi = __expf(mrow[st*2+1] - mn_hi);
            mrow[st*2+0] = mn_lo; mrow[st*2+1] = mn_hi;

            float rs_lo = 0.0f, rs_hi = 0.0f;
            float* Pw = Ps + (w * 32 + st * 16 + grp) * PPITCH;
            #pragma unroll
            for (int ni = 0; ni < 8; ni++) {
                float p0 = __expf(acc_s[st][ni][0] - mn_lo);
                float p1 = __expf(acc_s[st][ni][1] - mn_lo);
                float p2 = __expf(acc_s[st][ni][2] - mn_hi);
                float p3 = __expf(acc_s[st][ni][3] - mn_hi);
                rs_lo += p0 + p1;
                rs_hi += p2 + p3;
                *(float2*)&Pw[ni * 8 + 2 * tig] =
                    make_float2(roundtf(p0), roundtf(p1));
                *(float2*)&Pw[8 * PPITCH + ni * 8 + 2 * tig] =
                    make_float2(roundtf(p2), roundtf(p3));
            }
            rs_lo += __shfl_xor_sync(0xffffffffu, rs_lo, 1);
            rs_lo += __shfl_xor_sync(0xffffffffu, rs_lo, 2);
            rs_hi += __shfl_xor_sync(0xffffffffu, rs_hi, 1);
            rs_hi += __shfl_xor_sync(0xffffffffu, rs_hi, 2);
            lrow[st*2+0] = lrow[st*2+0] * f_lo + rs_lo;
            lrow[st*2+1] = lrow[st*2+1] * f_hi + rs_hi;

            #pragma unroll
            for (int ni = 0; ni < 8; ni++) {
                acc_o[st][ni][0] *= f_lo; acc_o[st][ni][1] *= f_lo;
                acc_o[st][ni][2] *= f_hi; acc_o[st][ni][3] *= f_hi;
            }
        }

        __syncwarp();

        // ---- O += P @ V (P via ldmatrix; V scalar, shared by both sets) ----
        #pragma unroll
        for (int kc = 0; kc < 8; kc++) {
            unsigned pa0[4], pa1[4];
            ldm_x4(pa0, pAddr + (kc * 8) * 4);
            ldm_x4(pa1, pAddr + (16 * PPITCH + kc * 8) * 4);
            unsigned bv[8][2];
            #pragma unroll
            for (int ni = 0; ni < 8; ni++) {
                const unsigned* p = Vs_ + (kc * 8 + tig) * VPITCH + ni * 8 + grp;
                bv[ni][0] = p[0];
                bv[ni][1] = p[4 * VPITCH];
            }
            #pragma unroll
            for (int ni = 0; ni < 8; ni++) {
                mma_tf32(acc_o[0][ni], pa0, bv[ni]);
                mma_tf32(acc_o[1][ni], pa1, bv[ni]);
            }
        }
        __syncwarp();
    }

    // ---- epilogue ----
    #pragma unroll
    for (int st = 0; st < 2; st++) {
        float il_lo = 1.0f / lrow[st*2+0];
        float il_hi = 1.0f / lrow[st*2+1];
        int qlo = qrow0 + st * 16;
        int qhi = qlo + 8;
        #pragma unroll
        for (int ni = 0; ni < 8; ni++) {
            int col = ni * 8 + 2 * tig;
            *(float2*)&Og[headoff + (size_t)qlo * DD + col] =
                make_float2(roundtf(acc_o[st][ni][0] * il_lo), roundtf(acc_o[st][ni][1] * il_lo));
            *(float2*)&Og[headoff + (size_t)qhi * DD + col] =
                make_float2(roundtf(acc_o[st][ni][2] * il_hi), roundtf(acc_o[st][ni][3] * il_hi));
        }
    }
}

// ---------------------------------------------------------------------------
extern "C" void kernel_launch(void* const* d_in, const int* in_sizes, int n_in,
                              void* d_out, int out_size)
{
    const float* x    = (const float*)d_in[0];
    const float* cosb = (const float*)d_in[1];
    const float* sinb = (const float*)d_in[2];
    const float* w_q  = (const float*)d_in[3];
    const float* w_k  = (const float*)d_in[4];
    const float* w_v  = (const float*)d_in[5];
    const float* w_o  = (const float*)d_in[6];
    float* out = (float*)d_out;

    float *q, *k, *v, *attn, *xr, *wr;
    cudaGetSymbolAddress((void**)&q,    g_q);
    cudaGetSymbolAddress((void**)&k,    g_k);
    cudaGetSymbolAddress((void**)&v,    g_v);
    cudaGetSymbolAddress((void**)&attn, g_attn);
    cudaGetSymbolAddress((void**)&xr,   g_xr);
    cudaGetSymbolAddress((void**)&wr,   g_wr);

    const int gm_smem = (2 * GA_TILE + 2 * GB_TILE) * sizeof(float);   // 110592
    cudaFuncSetAttribute(gemm_qkv_kernel,
                         cudaFuncAttributeMaxDynamicSharedMemorySize, gm_smem);
    cudaFuncSetAttribute(gemm_out_kernel,
                         cudaFuncAttributeMaxDynamicSharedMemorySize, gm_smem);

    const int fa_smem = (2 * KS_BUF + 2 * VS_BUF + 128 * PPITCH) * sizeof(float);
    cudaFuncSetAttribute(flash_attn_tc_kernel,
                         cudaFuncAttributeMaxDynamicSharedMemorySize, fa_smem);

    round_x_kernel<<<(MTOT * DD / 4) / 256, 256>>>(x, xr);
    round_w_kernel<<<(4 * DD * DD / 4) / 256, 256>>>(w_q, w_k, w_v, w_o, wr);

    // fused QKV projection + RoPE
    dim3 qkvgrid(DD / 128, MTOT / 256, 3);   // (8, 32, 3)
    gemm_qkv_kernel<<<qkvgrid, 256, gm_smem>>>(xr, wr, q, k, v, cosb, sinb);

    flash_attn_tc_kernel<<<dim3(TT / 128, BB * HH), 128, fa_smem>>>(q, k, v, attn);

    dim3 ogrid(DD / 128, MTOT / 256);        // (8, 32)
    gemm_out_kernel<<<ogrid, 256, gm_smem>>>(attn, wr + (size_t)3 * DD * DD, out);
}

// round 14
// speedup vs baseline: 1.0619x; 1.0209x over previous
#include <cuda_runtime.h>
#include <cuda_bf16.h>
#include <math.h>

#define BB 4
#define TT 2048
#define DD 1024
#define HH 16
#define HD 64
#define MTOT (BB*TT)          // 8192

// GEMM tiling: CTA 256x128, warp tile 64x64, 8 warps (4m x 2n), ldmatrix frags
#define GPITCH 36
#define GA_TILE (256*GPITCH)
#define GB_TILE (128*GPITCH)

// flash tiling (4 warps x 32 q-rows, ldmatrix frags)  [R13 measured-best]
#define KPITCH 68
#define VPITCH 72
#define PPITCH 68
#define KS_BUF (64*KPITCH)
#define VS_BUF (64*VPITCH)

__device__ float g_q[MTOT * DD];
__device__ float g_k[MTOT * DD];
__device__ float g_v[MTOT * DD];
__device__ float g_attn[MTOT * DD];
__device__ float g_xr[MTOT * DD];     // tf32-rounded x
__device__ float g_wr[4 * DD * DD];   // tf32-rounded w_q,w_k,w_v,w_o

// ---------------------------------------------------------------------------
__device__ __forceinline__ unsigned smem_u32(const void* p) {
    unsigned r;
    asm("{ .reg .u64 t; cvta.to.shared.u64 t, %1; cvt.u32.u64 %0, t; }"
        : "=r"(r) : "l"(p));
    return r;
}
__device__ __forceinline__ void cp_async16(unsigned s, const void* g) {
    asm volatile("cp.async.cg.shared.global [%0], [%1], 16;" :: "r"(s), "l"(g));
}
__device__ __forceinline__ void cp_commit() { asm volatile("cp.async.commit_group;"); }
__device__ __forceinline__ void cp_wait0()  { asm volatile("cp.async.wait_group 0;"); }
__device__ __forceinline__ unsigned f2tf32(float f) {
    unsigned u;
    asm("cvt.rna.tf32.f32 %0, %1;" : "=r"(u) : "f"(f));
    return u;
}
__device__ __forceinline__ float roundtf(float f) { return __uint_as_float(f2tf32(f)); }
__device__ __forceinline__ void mma_tf32(float* c, const unsigned* a, const unsigned* b) {
    asm volatile(
        "mma.sync.aligned.m16n8k8.row.col.f32.tf32.tf32.f32 "
        "{%0,%1,%2,%3}, {%4,%5,%6,%7}, {%8,%9}, {%0,%1,%2,%3};"
        : "+f"(c[0]), "+f"(c[1]), "+f"(c[2]), "+f"(c[3])
        : "r"(a[0]), "r"(a[1]), "r"(a[2]), "r"(a[3]), "r"(b[0]), "r"(b[1]));
}
// one ldmatrix.x4 = four 8x4-b32 tiles; lane L gets element (L/4, L%4)
__device__ __forceinline__ void ldm_x4(unsigned* r, unsigned addr) {
    asm volatile("ldmatrix.sync.aligned.m8n8.x4.shared.b16 {%0,%1,%2,%3}, [%4];"
        : "=r"(r[0]), "=r"(r[1]), "=r"(r[2]), "=r"(r[3]) : "r"(addr) : "memory");
}

// ---------------------------------------------------------------------------
// prep: round arrays to tf32 grid
// ---------------------------------------------------------------------------
__global__ __launch_bounds__(256) void round_x_kernel(const float* __restrict__ in,
                                                      float* __restrict__ out)
{
    int i = blockIdx.x * blockDim.x + threadIdx.x;
    float4 v = ((const float4*)in)[i];
    v.x = roundtf(v.x); v.y = roundtf(v.y); v.z = roundtf(v.z); v.w = roundtf(v.w);
    ((float4*)out)[i] = v;
}
__global__ __launch_bounds__(256) void round_w_kernel(
    const float* __restrict__ w0, const float* __restrict__ w1,
    const float* __restrict__ w2, const float* __restrict__ w3,
    float* __restrict__ out)
{
    int i = blockIdx.x * blockDim.x + threadIdx.x;
    const int per = DD * DD / 4;
    int which = i / per;
    int off   = i - which * per;
    const float* src = (which == 0) ? w0 : (which == 1) ? w1 : (which == 2) ? w2 : w3;
    float4 v = ((const float4*)src)[off];
    v.x = roundtf(v.x); v.y = roundtf(v.y); v.z = roundtf(v.z); v.w = roundtf(v.w);
    ((float4*)out)[i] = v;
}

// ---------------------------------------------------------------------------
// TF32 GEMM body: CTA 256x128, warp tile 64x64, ldmatrix fragments.
// Optional fused RoPE epilogue.
// ---------------------------------------------------------------------------
template<bool ROUND_OUT>
__device__ __forceinline__ void gemm_body(
    const float* __restrict__ A, const float* __restrict__ Bw,
    float* __restrict__ C, int M, int N, int K, float* sm,
    bool do_rope, const float* __restrict__ cosb, const float* __restrict__ sinb)
{
    float* sA = sm;                      // [2][256][GPITCH]
    float* sB = sm + 2 * GA_TILE;        // [2][128][GPITCH]

    const int tid  = threadIdx.x;
    const int lane = tid & 31;
    const int wid  = tid >> 5;
    const int wm   = wid & 3;
    const int wn   = wid >> 2;
    const int bm   = blockIdx.y * 256;
    const int bn   = blockIdx.x * 128;
    const int grp  = lane >> 2;
    const int tig  = lane & 3;

    const unsigned uA = smem_u32(sA);
    const unsigned uB = smem_u32(sB);

    // ldmatrix lane addressing (validated in R10 GEMM / R10+R13 flash)
    const int l15  = lane & 15;                         // A-pattern row
    const int lhi  = (lane >> 4) & 1;                   // A-pattern col sel
    const int brow = (lane & 7) + ((lane & 16) ? 8 : 0);// B-pattern row
    const int bsel = (lane & 8) ? 4 : 0;                // B-pattern col sel
    const unsigned aAddr = uA + (((wm * 64 + l15) * GPITCH) + lhi * 4) * 4;
    const unsigned bAddr = uB + (((wn * 64 + brow) * GPITCH) + bsel) * 4;

    float acc[4][8][4] = {};
    const int NK = K / 32;

    {
        #pragma unroll
        for (int i = 0; i < 8; i++) {
            int idx = tid + 256 * i;
            int row = idx >> 3;
            int c4  = idx & 7;
            cp_async16(uA + (row * GPITCH + c4 * 4) * 4,
                       A + (size_t)(bm + row) * K + c4 * 4);
        }
        #pragma unroll
        for (int i = 0; i < 4; i++) {
            int idx = tid + 256 * i;
            int row = idx >> 3;
            int c4  = idx & 7;
            cp_async16(uB + (row * GPITCH + c4 * 4) * 4,
                       Bw + (size_t)(bn + row) * K + c4 * 4);
        }
        cp_commit();
    }

    for (int kt = 0; kt < NK; kt++) {
        cp_wait0();
        __syncthreads();

        int nxt = kt + 1;
        if (nxt < NK) {
            int nb = nxt & 1;
            #pragma unroll
            for (int i = 0; i < 8; i++) {
                int idx = tid + 256 * i;
                int row = idx >> 3;
                int c4  = idx & 7;
                cp_async16(uA + (nb * GA_TILE + row * GPITCH + c4 * 4) * 4,
                           A + (size_t)(bm + row) * K + nxt * 32 + c4 * 4);
            }
            #pragma unroll
            for (int i = 0; i < 4; i++) {
                int idx = tid + 256 * i;
                int row = idx >> 3;
                int c4  = idx & 7;
                cp_async16(uB + (nb * GB_TILE + row * GPITCH + c4 * 4) * 4,
                           Bw + (size_t)(bn + row) * K + nxt * 32 + c4 * 4);
            }
            cp_commit();
        }

        const unsigned aBuf = aAddr + (kt & 1) * GA_TILE * 4;
        const unsigned bBuf = bAddr + (kt & 1) * GB_TILE * 4;

        #pragma unroll
        for (int ks = 0; ks < 4; ks++) {
            unsigned a[4][4], b[8][2];
            #pragma unroll
            for (int mi = 0; mi < 4; mi++)
                ldm_x4(a[mi], aBuf + (mi * 16 * GPITCH + ks * 8) * 4);
            #pragma unroll
            for (int pr = 0; pr < 4; pr++) {
                unsigned t[4];
                ldm_x4(t, bBuf + (pr * 16 * GPITCH + ks * 8) * 4);
                b[2*pr][0] = t[0]; b[2*pr][1] = t[1];
                b[2*pr+1][0] = t[2]; b[2*pr+1][1] = t[3];
            }
            #pragma unroll
            for (int mi = 0; mi < 4; mi++)
                #pragma unroll
                for (int ni = 0; ni < 8; ni++)
                    mma_tf32(acc[mi][ni], a[mi], b[ni]);
        }
    }

    if (do_rope) {
        #pragma unroll
        for (int mi = 0; mi < 4; mi++) {
            int r0 = bm + wm * 64 + mi * 16 + grp;
            int t0 = r0 & (TT - 1);
            int t1 = (r0 + 8) & (TT - 1);
            #pragma unroll
            for (int ni = 0; ni < 4; ni++) {
                int d   = ni * 8 + tig * 2;
                int col = bn + wn * 64 + d;
                float2 cl0 = *(const float2*)&cosb[t0 * HD + d];
                float2 ch0 = *(const float2*)&cosb[t0 * HD + d + 32];
                float2 sl0 = *(const float2*)&sinb[t0 * HD + d];
                float2 sh0 = *(const float2*)&sinb[t0 * HD + d + 32];
                float2 cl1 = *(const float2*)&cosb[t1 * HD + d];
                float2 ch1 = *(const float2*)&cosb[t1 * HD + d + 32];
                float2 sl1 = *(const float2*)&sinb[t1 * HD + d];
                float2 sh1 = *(const float2*)&sinb[t1 * HD + d + 32];

                float x1, x2;
                x1 = acc[mi][ni][0];   x2 = acc[mi][ni + 4][0];
                float o00 = x1 * cl0.x - x2 * sl0.x;
                float o04 = x2 * ch0.x + x1 * sh0.x;
                x1 = acc[mi][ni][1];   x2 = acc[mi][ni + 4][1];
                float o01 = x1 * cl0.y - x2 * sl0.y;
                float o05 = x2 * ch0.y + x1 * sh0.y;
                x1 = acc[mi][ni][2];   x2 = acc[mi][ni + 4][2];
                float o02 = x1 * cl1.x - x2 * sl1.x;
                float o06 = x2 * ch1.x + x1 * sh1.x;
                x1 = acc[mi][ni][3];   x2 = acc[mi][ni + 4][3];
                float o03 = x1 * cl1.y - x2 * sl1.y;
                float o07 = x2 * ch1.y + x1 * sh1.y;

                *(float2*)&C[(size_t)r0 * N + col] =
                    make_float2(roundtf(o00), roundtf(o01));
                *(float2*)&C[(size_t)(r0 + 8) * N + col] =
                    make_float2(roundtf(o02), roundtf(o03));
                *(float2*)&C[(size_t)r0 * N + col + 32] =
                    make_float2(roundtf(o04), roundtf(o05));
                *(float2*)&C[(size_t)(r0 + 8) * N + col + 32] =
                    make_float2(roundtf(o06), roundtf(o07));
            }
        }
    } else {
        #pragma unroll
        for (int mi = 0; mi < 4; mi++) {
            int r0 = bm + wm * 64 + mi * 16 + grp;
            #pragma unroll
            for (int ni = 0; ni < 8; ni++) {
                int col = bn + wn * 64 + ni * 8 + tig * 2;
                float2 lo, hi;
                if (ROUND_OUT) {
                    lo = make_float2(roundtf(acc[mi][ni][0]), roundtf(acc[mi][ni][1]));
                    hi = make_float2(roundtf(acc[mi][ni][2]), roundtf(acc[mi][ni][3]));
                } else {
                    lo = make_float2(acc[mi][ni][0], acc[mi][ni][1]);
                    hi = make_float2(acc[mi][ni][2], acc[mi][ni][3]);
                }
                *(float2*)&C[(size_t)r0 * N + col]       = lo;
                *(float2*)&C[(size_t)(r0 + 8) * N + col] = hi;
            }
        }
    }
}

__global__ __launch_bounds__(256) void gemm_qkv_kernel(
    const float* __restrict__ A, const float* __restrict__ W,
    float* __restrict__ Cq, float* __restrict__ Ck, float* __restrict__ Cv,
    const float* __restrict__ cosb, const float* __restrict__ sinb)
{
    extern __shared__ float sm[];
    int z = blockIdx.z;
    float* C = (z == 0) ? Cq : (z == 1) ? Ck : Cv;
    gemm_body<true>(A, W + (size_t)z * DD * DD, C, MTOT, DD, DD, sm,
                    /*do_rope=*/(z != 2), cosb, sinb);
}
__global__ __launch_bounds__(256) void gemm_out_kernel(
    const float* __restrict__ A, const float* __restrict__ W, float* __restrict__ C)
{
    extern __shared__ float sm[];
    gemm_body<false>(A, W, C, MTOT, DD, DD, sm, false, nullptr, nullptr);
}

// ---------------------------------------------------------------------------
// Tensor-core causal flash attention (R13 measured-best, untouched).
// BQ=128, 4 warps x 32 q-rows. Q/K/P fragments via ldmatrix; V scalar.
// ---------------------------------------------------------------------------
__global__ __launch_bounds__(128) void flash_attn_tc_kernel(
    const float* __restrict__ Qg, const float* __restrict__ Kg,
    const float* __restrict__ Vg, float* __restrict__ Og)
{
    extern __shared__ float sm[];
    float* Ks = sm;
    float* Vs = Ks + 2 * KS_BUF;
    float* Ps = Vs + 2 * VS_BUF;          // [128][PPITCH]

    const int tid  = threadIdx.x;
    const int lane = tid & 31;
    const int w    = tid >> 5;            // warp 0..3
    const int grp  = lane >> 2;
    const int tig  = lane & 3;
    const int qb   = (TT/128 - 1) - blockIdx.x;   // descending work order
    const int bh   = blockIdx.y;
    const int b    = bh >> 4;
    const int h    = bh & 15;

    const size_t headoff = (size_t)(b * TT) * DD + (size_t)h * HD;
    const float scale = 0.125f;
    const unsigned uK = smem_u32(Ks);
    const unsigned uV = smem_u32(Vs);
    const unsigned uP = smem_u32(Ps);

    const int l15  = lane & 15;
    const int lhi  = (lane >> 4) & 1;
    const int brow = (lane & 7) + ((lane & 16) ? 8 : 0);
    const int bsel = (lane & 8) ? 4 : 0;
    const unsigned kAddr = uK + ((brow * KPITCH) + bsel) * 4;
    const unsigned pAddr = uP + (((w * 32 + l15) * PPITCH) + lhi * 4) * 4;

    #pragma unroll
    for (int i = 0; i < 16; i++) {
        int idx = i * 128 + tid;
        int row = idx >> 4;
        int c4  = idx & 15;
        float4 v4 = *(const float4*)&Qg[headoff + (size_t)(qb*128 + row) * DD + c4*4];
        *(float4*)&Ps[row * PPITCH + c4*4] = v4;
    }
    __syncthreads();

    unsigned qa[2][8][4];
    #pragma unroll
    for (int st = 0; st < 2; st++)
        #pragma unroll
        for (int ks = 0; ks < 8; ks++)
            ldm_x4(qa[st][ks], pAddr + (st * 16 * PPITCH + ks * 8) * 4);
    __syncwarp();

    float acc_o[2][8][4] = {};
    float mrow[4] = {-1e30f, -1e30f, -1e30f, -1e30f};
    float lrow[4] = {};

    const int kb_max = 2 * qb + 1;
    const int qrow0 = qb * 128 + w * 32 + grp;

    {
        #pragma unroll
        for (int i = 0; i < 16; i++) {
            int idx = i * 128 + tid;
            int row = (idx >> 4) & 63;
            int c4  = idx & 15;
            size_t goff = headoff + (size_t)row * DD + c4 * 4;
            if (idx < 1024)
                cp_async16(uK + (row * KPITCH + c4 * 4) * 4, Kg + goff);
            else
                cp_async16(uV + (row * VPITCH + c4 * 4) * 4, Vg + goff);
        }
        cp_commit();
    }

    for (int kb = 0; kb <= kb_max; kb++) {
        cp_wait0();
        __syncthreads();

        if (kb < kb_max) {
            int nb = (kb + 1) & 1;
            #pragma unroll
            for (int i = 0; i < 16; i++) {
                int idx = i * 128 + tid;
                int row = (idx >> 4) & 63;
                int c4  = idx & 15;
                size_t goff = headoff + (size_t)((kb+1)*64 + row) * DD + c4 * 4;
                if (idx < 1024)
                    cp_async16(uK + (nb * KS_BUF + row * KPITCH + c4 * 4) * 4, Kg + goff);
                else
                    cp_async16(uV + (nb * VS_BUF + row * VPITCH + c4 * 4) * 4, Vg + goff);
            }
            cp_commit();
        }

        const unsigned kBuf = kAddr + (kb & 1) * KS_BUF * 4;
        const unsigned* Vs_ = (const unsigned*)(Vs + (kb & 1) * VS_BUF);

        float acc_s[2][8][4] = {};
        #pragma unroll
        for (int ks = 0; ks < 8; ks++) {
            unsigned bfr[8][2];
            #pragma unroll
            for (int pr = 0; pr < 4; pr++) {
                unsigned t[4];
                ldm_x4(t, kBuf + (pr * 16 * KPITCH + ks * 8) * 4);
                bfr[2*pr][0] = t[0]; bfr[2*pr][1] = t[1];
                bfr[2*pr+1][0] = t[2]; bfr[2*pr+1][1] = t[3];
            }
            #pragma unroll
            for (int ni = 0; ni < 8; ni++) {
                mma_tf32(acc_s[0][ni], qa[0][ks], bfr[ni]);
                mma_tf32(acc_s[1][ni], qa[1][ks], bfr[ni]);
            }
        }

        const bool diag = (kb >= 2 * qb);
        #pragma unroll
        for (int st = 0; st < 2; st++) {
            int qlo = qrow0 + st * 16;
            int qhi = qlo + 8;
            #pragma unroll
            for (int ni = 0; ni < 8; ni++) {
                int k0 = kb * 64 + ni * 8 + 2 * tig;
                if (diag) {
                    acc_s[st][ni][0] = (k0     <= qlo) ? acc_s[st][ni][0] * scale : -1e30f;
                    acc_s[st][ni][1] = (k0 + 1 <= qlo) ? acc_s[st][ni][1] * scale : -1e30f;
                    acc_s[st][ni][2] = (k0     <= qhi) ? acc_s[st][ni][2] * scale : -1e30f;
                    acc_s[st][ni][3] = (k0 + 1 <= qhi) ? acc_s[st][ni][3] * scale : -1e30f;
                } else {
                    acc_s[st][ni][0] *= scale; acc_s[st][ni][1] *= scale;
                    acc_s[st][ni][2] *= scale; acc_s[st][ni][3] *= scale;
                }
            }
        }

        #pragma unroll
        for (int st = 0; st < 2; st++) {
            float tm_lo = -1e30f, tm_hi = -1e30f;
            #pragma unroll
            for (int ni = 0; ni < 8; ni++) {
                tm_lo = fmaxf(tm_lo, fmaxf(acc_s[st][ni][0], acc_s[st][ni][1]));
                tm_hi = fmaxf(tm_hi, fmaxf(acc_s[st][ni][2], acc_s[st][ni][3]));
            }
            tm_lo = fmaxf(tm_lo, __shfl_xor_sync(0xffffffffu, tm_lo, 1));
            tm_lo = fmaxf(tm_lo, __shfl_xor_sync(0xffffffffu, tm_lo, 2));
            tm_hi = fmaxf(tm_hi, __shfl_xor_sync(0xffffffffu, tm_hi, 1));
            tm_hi = fmaxf(tm_hi, __shfl_xor_sync(0xffffffffu, tm_hi, 2));

            float mn_lo = fmaxf(mrow[st*2+0], tm_lo);
            float mn_hi = fmaxf(mrow[st*2+1], tm_hi);
            float f_lo = __expf(mrow[st*2+0] - mn_lo);
            float f_hi = __expf(mrow[st*2+1] - mn_hi);
            mrow[st*2+0] = mn_lo; mrow[st*2+1] = mn_hi;

            float rs_lo = 0.0f, rs_hi = 0.0f;
            float* Pw = Ps + (w * 32 + st * 16 + grp) * PPITCH;
            #pragma unroll
            for (int ni = 0; ni < 8; ni++) {
                float p0 = __expf(acc_s[st][ni][0] - mn_lo);
                float p1 = __expf(acc_s[st][ni][1] - mn_lo);
                float p2 = __expf(acc_s[st][ni][2] - mn_hi);
                float p3 = __expf(acc_s[st][ni][3] - mn_hi);
                rs_lo += p0 + p1;
                rs_hi += p2 + p3;
                *(float2*)&Pw[ni * 8 + 2 * tig] =
                    make_float2(roundtf(p0), roundtf(p1));
                *(float2*)&Pw[8 * PPITCH + ni * 8 + 2 * tig] =
                    make_float2(roundtf(p2), roundtf(p3));
            }
            rs_lo += __shfl_xor_sync(0xffffffffu, rs_lo, 1);
            rs_lo += __shfl_xor_sync(0xffffffffu, rs_lo, 2);
            rs_hi += __shfl_xor_sync(0xffffffffu, rs_hi, 1);
            rs_hi += __shfl_xor_sync(0xffffffffu, rs_hi, 2);
            lrow[st*2+0] = lrow[st*2+0] * f_lo + rs_lo;
            lrow[st*2+1] = lrow[st*2+1] * f_hi + rs_hi;

            #pragma unroll
            for (int ni = 0; ni < 8; ni++) {
                acc_o[st][ni][0] *= f_lo; acc_o[st][ni][1] *= f_lo;
                acc_o[st][ni][2] *= f_hi; acc_o[st][ni][3] *= f_hi;
            }
        }

        __syncwarp();

        #pragma unroll
        for (int kc = 0; kc < 8; kc++) {
            unsigned pa0[4], pa1[4];
            ldm_x4(pa0, pAddr + (kc * 8) * 4);
            ldm_x4(pa1, pAddr + (16 * PPITCH + kc * 8) * 4);
            unsigned bv[8][2];
            #pragma unroll
            for (int ni = 0; ni < 8; ni++) {
                const unsigned* p = Vs_ + (kc * 8 + tig) * VPITCH + ni * 8 + grp;
                bv[ni][0] = p[0];
                bv[ni][1] = p[4 * VPITCH];
            }
            #pragma unroll
            for (int ni = 0; ni < 8; ni++) {
                mma_tf32(acc_o[0][ni], pa0, bv[ni]);
                mma_tf32(acc_o[1][ni], pa1, bv[ni]);
            }
        }
        __syncwarp();
    }

    #pragma unroll
    for (int st = 0; st < 2; st++) {
        float il_lo = 1.0f / lrow[st*2+0];
        float il_hi = 1.0f / lrow[st*2+1];
        int qlo = qrow0 + st * 16;
        int qhi = qlo + 8;
        #pragma unroll
        for (int ni = 0; ni < 8; ni++) {
            int col = ni * 8 + 2 * tig;
            *(float2*)&Og[headoff + (size_t)qlo * DD + col] =
                make_float2(roundtf(acc_o[st][ni][0] * il_lo), roundtf(acc_o[st][ni][1] * il_lo));
            *(float2*)&Og[headoff + (size_t)qhi * DD + col] =
                make_float2(roundtf(acc_o[st][ni][2] * il_hi), roundtf(acc_o[st][ni][3] * il_hi));
        }
    }
}

// ---------------------------------------------------------------------------
extern "C" void kernel_launch(void* const* d_in, const int* in_sizes, int n_in,
                              void* d_out, int out_size)
{
    const float* x    = (const float*)d_in[0];
    const float* cosb = (const float*)d_in[1];
    const float* sinb = (const float*)d_in[2];
    const float* w_q  = (const float*)d_in[3];
    const float* w_k  = (const float*)d_in[4];
    const float* w_v  = (const float*)d_in[5];
    const float* w_o  = (const float*)d_in[6];
    float* out = (float*)d_out;

    float *q, *k, *v, *attn, *xr, *wr;
    cudaGetSymbolAddress((void**)&q,    g_q);
    cudaGetSymbolAddress((void**)&k,    g_k);
    cudaGetSymbolAddress((void**)&v,    g_v);
    cudaGetSymbolAddress((void**)&attn, g_attn);
    cudaGetSymbolAddress((void**)&xr,   g_xr);
    cudaGetSymbolAddress((void**)&wr,   g_wr);

    const int gm_smem = (2 * GA_TILE + 2 * GB_TILE) * sizeof(float);   // 110592
    cudaFuncSetAttribute(gemm_qkv_kernel,
                         cudaFuncAttributeMaxDynamicSharedMemorySize, gm_smem);
    cudaFuncSetAttribute(gemm_out_kernel,
                         cudaFuncAttributeMaxDynamicSharedMemorySize, gm_smem);

    const int fa_smem = (2 * KS_BUF + 2 * VS_BUF + 128 * PPITCH) * sizeof(float);
    cudaFuncSetAttribute(flash_attn_tc_kernel,
                         cudaFuncAttributeMaxDynamicSharedMemorySize, fa_smem);

    round_x_kernel<<<(MTOT * DD / 4) / 256, 256>>>(x, xr);
    round_w_kernel<<<(4 * DD * DD / 4) / 256, 256>>>(w_q, w_k, w_v, w_o, wr);

    // fused QKV projection + RoPE
    dim3 qkvgrid(DD / 128, MTOT / 256, 3);   // (8, 32, 3)
    gemm_qkv_kernel<<<qkvgrid, 256, gm_smem>>>(xr, wr, q, k, v, cosb, sinb);

    flash_attn_tc_kernel<<<dim3(TT / 128, BB * HH), 128, fa_smem>>>(q, k, v, attn);

    dim3 ogrid(DD / 128, MTOT / 256);        // (8, 32)
    gemm_out_kernel<<<ogrid, 256, gm_smem>>>(attn, wr + (size_t)3 * DD * DD, out);
}